// round 13
// baseline (speedup 1.0000x reference)
#include <cuda_runtime.h>
#include <math.h>

#define BN 4
#define HW 25600
#define Wd 160
#define PRE_K 2048
#define TOPK 500
#define NT1 1024

#define OFF_MASK (BN*HW)                 /* 102400 */
#define OFF_BOX  (OFF_MASK + BN*4*HW)    /* 512000 */
#define OFF_VAL  (OFF_BOX + BN*TOPK*4)   /* 520000 */

// ---------------- scratch (device globals; no allocation) ----------------
__device__ float               d_score[BN][HW];
__device__ float4              d_boxes4[BN][HW];
__device__ unsigned long long  d_vkey[BN][HW];      // fallback path only
__device__ float               d_cscore[BN][PRE_K];
__device__ float4              d_cbox[BN][PRE_K];
__device__ unsigned long long  d_mask[BN][PRE_K][32];
__device__ int                 d_Vc[BN];
__device__ int                 d_Nk[BN];
__device__ float4              d_hp4[BN][TOPK];
__device__ float               d_hlnp[BN][TOPK];

// ---------------- K1: f32 softmax score + boxes + fused mask pass-through ----------------
__global__ void __launch_bounds__(256) k1_score(const float* __restrict__ mask,
                                                const float* __restrict__ bias,
                                                float* __restrict__ out)
{
    int idx = blockIdx.x * 256 + threadIdx.x;       // one thread = 4 consecutive pixels
    if (idx >= BN * (HW / 4)) return;
    int b = idx / (HW / 4), q = idx - b * (HW / 4);
    int p = q * 4;
    const int q4 = HW / 4;
    const float4* mk = (const float4*)(mask + (size_t)b * 4 * HW);
    const float4* bi = (const float4*)(bias + (size_t)b * 4 * HW);
    float4* mo = (float4*)(out + OFF_MASK + (size_t)b * 4 * HW);
    float4 m0 = mk[q], m1 = mk[q4 + q], m2 = mk[2*q4 + q], m3 = mk[3*q4 + q];
    float4 g0 = bi[q], g1 = bi[q4 + q], g2 = bi[2*q4 + q], g3 = bi[3*q4 + q];
    mo[q] = m0; mo[q4 + q] = m1; mo[2*q4 + q] = m2; mo[3*q4 + q] = m3;   // pass-through
    float c0[4] = {m0.x, m0.y, m0.z, m0.w};
    float c1[4] = {m1.x, m1.y, m1.z, m1.w};
    float c2[4] = {m2.x, m2.y, m2.z, m2.w};
    float c3[4] = {m3.x, m3.y, m3.z, m3.w};
    float h0[4] = {g0.x, g0.y, g0.z, g0.w};
    float h1[4] = {g1.x, g1.y, g1.z, g1.w};
    float h2[4] = {g2.x, g2.y, g2.z, g2.w};
    float h3[4] = {g3.x, g3.y, g3.z, g3.w};
    float y = (float)(p / Wd);                       // 160%4==0 -> same row for all 4
    float xb = (float)(p % Wd);
    float sout[4];
    #pragma unroll
    for (int u = 0; u < 4; u++) {
        float x0 = c0[u], x1 = c1[u], x2 = c2[u], x3 = c3[u];
        float mm = x0; int cl = 0;
        if (x1 > mm) { mm = x1; cl = 1; }
        if (x2 > mm) { mm = x2; cl = 2; }
        if (x3 > mm) { mm = x3; cl = 3; }
        float e0 = expf(x0 - mm), e1 = expf(x1 - mm), e2 = expf(x2 - mm), e3 = expf(x3 - mm);
        float s = ((e0 + e1) + e2) + e3;
        float prob = 1.0f / s;
        bool fr = (cl != 0) && (prob > 0.75f);
        sout[u] = fr ? prob : -1.0f;
        float xx = xb + (float)u;
        d_boxes4[b][p + u] = make_float4(y + h0[u], xx + h1[u], y + h2[u], xx + h3[u]);
    }
    ((float4*)&d_score[b][0])[q] = make_float4(sout[0], sout[1], sout[2], sout[3]);
}

// ---------------- KB1: compact + bitonic top-2048 sort + padding (per image) ----------------
__global__ void __launch_bounds__(NT1) kb1_sort()
{
    __shared__ unsigned long long skey[PRE_K];      // 16 KB
    __shared__ int spad[PRE_K];                     // 8 KB
    __shared__ int sprefV[800];
    __shared__ int swsum[32];
    __shared__ int sTot;
    int b = blockIdx.x;
    int t = threadIdx.x, lane = t & 31, w = t >> 5;

    unsigned flags = 0;
    unsigned kb[25];
    #pragma unroll
    for (int c = 0; c < 25; c++) {
        float sc = d_score[b][c * NT1 + t];
        bool fv = sc > 0.0f;
        kb[c] = ~__float_as_uint(sc);
        flags |= (fv ? 1u : 0u) << c;
        unsigned bal = __ballot_sync(0xffffffffu, fv);
        if (lane == 0) sprefV[c * 32 + w] = __popc(bal);
    }
    __syncthreads();

    int cnt = (t < 800) ? sprefV[t] : 0;
    int inc = cnt;
    #pragma unroll
    for (int off = 1; off < 32; off <<= 1) {
        int u = __shfl_up_sync(0xffffffffu, inc, off);
        if (lane >= off) inc += u;
    }
    if (lane == 31) swsum[w] = inc;
    __syncthreads();
    if (w == 0) {
        int v2 = swsum[lane], i2 = v2;
        #pragma unroll
        for (int off = 1; off < 32; off <<= 1) {
            int u = __shfl_up_sync(0xffffffffu, i2, off);
            if (lane >= off) i2 += u;
        }
        swsum[lane] = i2 - v2;
        if (lane == 31) sTot = i2;
    }
    __syncthreads();
    int excl = swsum[w] + inc - cnt;
    if (t < 800) sprefV[t] = excl;
    __syncthreads();
    int V  = sTot;
    int Vc = V < PRE_K ? V : PRE_K;

    #pragma unroll
    for (int c = 0; c < 25; c++) {
        bool fv = (flags >> c) & 1u;
        unsigned bal = __ballot_sync(0xffffffffu, fv);
        int pvL = __popc(bal & ((1u << lane) - 1u));
        int e  = c * 32 + w;
        int pe = sprefV[e];
        int p  = c * NT1 + t;
        if (fv) {
            int posV = pe + pvL;
            unsigned long long key = (((unsigned long long)kb[c]) << 32) | (unsigned)p;
            if (V <= PRE_K) skey[posV] = key;
            else            d_vkey[b][posV] = key;
        } else {
            int posI = (e << 5) - pe + (lane - pvL);
            if (posI < PRE_K) spad[posI] = p;
        }
    }
    __syncthreads();

    if (V <= PRE_K) {
        int P = 1; while (P < V) P <<= 1;
        for (int s = V + t; s < P; s += NT1) skey[s] = ~0ull;
        __syncthreads();
        for (unsigned ksz = 2; ksz <= (unsigned)P; ksz <<= 1) {
            for (unsigned j = ksz >> 1; j; j >>= 1) {
                unsigned tt = (unsigned)t;
                if (tt < (unsigned)(P >> 1)) {
                    unsigned i  = ((tt & ~(j - 1)) << 1) | (tt & (j - 1));
                    unsigned pr = i | j;
                    bool asc = (i & ksz) == 0;
                    unsigned long long a = skey[i], cc = skey[pr];
                    if ((a > cc) == asc) { skey[i] = cc; skey[pr] = a; }
                }
                __syncthreads();
            }
        }
        for (int s = t; s < PRE_K; s += NT1) {
            int p; float sc_;
            if (s < Vc) {
                unsigned long long k = skey[s];
                p   = (int)(k & 0xffffffffu);
                sc_ = __uint_as_float(~(unsigned)(k >> 32));
            } else {
                p   = spad[s - Vc];
                sc_ = -1.0f;
            }
            d_cscore[b][s] = sc_;
            d_cbox[b][s]   = d_boxes4[b][p];
        }
    } else {
        int nR = (V + NT1 - 1) / NT1;
        for (int r0 = 0; r0 < nR; r0++) {
            int e = r0 * NT1 + t;
            unsigned long long ke = (e < V) ? d_vkey[b][e] : 0ull;
            int rk = 0;
            for (int base = 0; base < V; base += PRE_K) {
                int n = V - base; if (n > PRE_K) n = PRE_K;
                __syncthreads();
                for (int qq = t; qq < n; qq += NT1) skey[qq] = d_vkey[b][base + qq];
                __syncthreads();
                if (e < V) for (int j = 0; j < n; j++) rk += (skey[j] < ke) ? 1 : 0;
            }
            __syncthreads();
            if (e < V && rk < PRE_K) {
                int p = (int)(ke & 0xffffffffu);
                d_cscore[b][rk] = __uint_as_float(~(unsigned)(ke >> 32));
                d_cbox[b][rk]   = d_boxes4[b][p];
            }
        }
    }
    if (t == 0) d_Vc[b] = Vc;
}

// ---------------- K5: suppression bit-mask matrix, 16 rows/block, cbox in shared ----------------
__global__ void __launch_bounds__(512) k5_iou()
{
    __shared__ float4 scbox[PRE_K];                 // 32 KB
    int b = blockIdx.y;
    int Vc = d_Vc[b];
    int i0 = blockIdx.x * 16;
    if (i0 >= Vc) return;
    int tid = threadIdx.x;
    for (int q = tid; q < Vc; q += 512) scbox[q] = d_cbox[b][q];
    __syncthreads();
    int r = tid >> 5, lane = tid & 31;
    int i = i0 + r;
    if (i >= Vc) return;
    float4 a = scbox[i];
    float areaA = (a.z - a.x) * (a.w - a.y);
    unsigned long long bits = 0;
    int j0 = lane << 6;
    int ks = i + 1 - j0; if (ks < 0) ks = 0;
    int ke = Vc - j0;    if (ke > 64) ke = 64;
    for (int k = ks; k < ke; k++) {
        float4 c = scbox[j0 + k];
        float areaB = (c.z - c.x) * (c.w - c.y);
        float lty = fmaxf(a.x, c.x), ltx = fmaxf(a.y, c.y);
        float rby = fminf(a.z, c.z), rbx = fminf(a.w, c.w);
        float wy = fmaxf(rby - lty, 0.0f), wx = fmaxf(rbx - ltx, 0.0f);
        float inter = wy * wx;
        float iou = inter / (areaA + areaB - inter);  // IEEE div: bit-matches reference decision
        if (iou > 0.5f) bits |= 1ull << k;
    }
    d_mask[b][i][lane] = bits;
}

// ---------------- KB2: exact greedy NMS, leader elimination, parallel reductions ----------------
__global__ void __launch_bounds__(1024) kb2_nms_select(float* __restrict__ out)
{
    __shared__ unsigned long long s_red[128][33];   // [chunk][word] (+pad) 33.8 KB
    __shared__ unsigned long long s_alive[32], s_kept[32], s_lead[32];
    __shared__ int s_flag[2];
    __shared__ int wpref[33];
    int b = blockIdx.x;
    int t = threadIdx.x;
    int Vc = d_Vc[b];
    int chunk = t >> 3;          // 128 chunks x 16 rows
    int slot  = t & 7;           // 8 slots x 4 words
    int w32 = t >> 5, l32 = t & 31;
    const unsigned long long* mrow = &d_mask[b][0][0];

    if (t < 32) {
        int hi = Vc - t * 64;
        unsigned long long a = 0;
        if (hi >= 64) a = ~0ull;
        else if (hi > 0) a = (1ull << hi) - 1ull;
        s_alive[t] = a;
        s_kept[t] = 0;
        if (t == 0) { s_flag[0] = (Vc > 0); s_flag[1] = 0; }
    }
    __syncthreads();

    for (int round = 0; round < PRE_K && s_flag[round & 1]; round++) {
        // ---- sweep 1: per-chunk OR of alive rows ----
        if (t == 0) s_flag[(round + 1) & 1] = 0;     // reset next-round flag (consumed already)
        {
            unsigned af = (unsigned)((s_alive[chunk >> 2] >> ((chunk & 3) * 16)) & 0xFFFFull);
            unsigned long long a0 = 0, a1 = 0, a2 = 0, a3 = 0;
            int rbase = chunk << 4;
            while (af) {
                int r = __ffs(af) - 1; af &= af - 1;
                const ulonglong2* p = (const ulonglong2*)(mrow + (size_t)(rbase + r) * 32 + slot * 4);
                ulonglong2 u = p[0], v = p[1];
                a0 |= u.x; a1 |= u.y; a2 |= v.x; a3 |= v.y;
            }
            s_red[chunk][slot*4+0] = a0; s_red[chunk][slot*4+1] = a1;
            s_red[chunk][slot*4+2] = a2; s_red[chunk][slot*4+3] = a3;
        }
        __syncthreads();
        // ---- parallel reduce: warp w reduces word w over 128 chunks ----
        {
            unsigned long long v = s_red[l32][w32] | s_red[l32+32][w32]
                                 | s_red[l32+64][w32] | s_red[l32+96][w32];
            #pragma unroll
            for (int off = 16; off; off >>= 1) v |= __shfl_xor_sync(0xffffffffu, v, off);
            if (l32 == 0) s_lead[w32] = s_alive[w32] & ~v;   // leaders: kept for sure
        }
        __syncthreads();
        // ---- sweep 2: per-chunk OR of leader rows ----
        {
            unsigned lf = (unsigned)((s_lead[chunk >> 2] >> ((chunk & 3) * 16)) & 0xFFFFull);
            unsigned long long a0 = 0, a1 = 0, a2 = 0, a3 = 0;
            int rbase = chunk << 4;
            while (lf) {
                int r = __ffs(lf) - 1; lf &= lf - 1;
                const ulonglong2* p = (const ulonglong2*)(mrow + (size_t)(rbase + r) * 32 + slot * 4);
                ulonglong2 u = p[0], v = p[1];
                a0 |= u.x; a1 |= u.y; a2 |= v.x; a3 |= v.y;
            }
            s_red[chunk][slot*4+0] = a0; s_red[chunk][slot*4+1] = a1;
            s_red[chunk][slot*4+2] = a2; s_red[chunk][slot*4+3] = a3;
        }
        __syncthreads();
        // ---- parallel reduce + state update ----
        {
            unsigned long long v = s_red[l32][w32] | s_red[l32+32][w32]
                                 | s_red[l32+64][w32] | s_red[l32+96][w32];
            #pragma unroll
            for (int off = 16; off; off >>= 1) v |= __shfl_xor_sync(0xffffffffu, v, off);
            if (l32 == 0) {
                unsigned long long lead = s_lead[w32];
                s_kept[w32] |= lead;
                unsigned long long na = s_alive[w32] & ~(lead | v);
                s_alive[w32] = na;
                if (na) atomicOr(&s_flag[(round + 1) & 1], 1);
            }
        }
        __syncthreads();
    }

    // ---- stable partition by keep flag == top_k(kept_s, 500) ----
    if (t == 0) {
        int run = 0;
        for (int w = 0; w < 32; w++) { wpref[w] = run; run += __popcll(s_kept[w]); }
        wpref[32] = run;
        d_Nk[b] = run < TOPK ? run : TOPK;
    }
    __syncthreads();
    int keptTotal = wpref[32];
    for (int slot2 = t; slot2 < PRE_K; slot2 += 1024) {
        int w = slot2 >> 6, bo = slot2 & 63;
        unsigned long long word = s_kept[w];
        int bit = (int)((word >> bo) & 1ull);
        int kb2 = wpref[w] + __popcll(word & ((1ull << bo) - 1ull));
        int r = bit ? kb2 : keptTotal + (slot2 - kb2);
        if (r < TOPK) {
            float4 bx = d_cbox[b][slot2];
            ((float4*)(out + OFF_BOX))[b * TOPK + r] = bx;
            out[OFF_VAL + b * TOPK + r] = bit ? 1.0f : 0.0f;
            if (bit) {
                float sc = d_cscore[b][slot2];
                float sy = bx.z - bx.x, sx = bx.w - bx.y;
                d_hp4[b][r] = make_float4((bx.x + bx.z) * 0.5f, (bx.y + bx.w) * 0.5f,
                                          10.0f / sy, 10.0f / sx);
                d_hlnp[b][r] = logf(sc);
            }
        }
    }
}

// ---------------- K8: tile-pruned heatmap (exact interval pruning per 16x16 tile) ----------------
__global__ void __launch_bounds__(256) k8_heat(float* __restrict__ out)
{
    int b = blockIdx.y;
    int tile = blockIdx.x;                          // 100 tiles of 16x16
    int ty0 = (tile / 10) * 16, tx0 = (tile % 10) * 16;
    __shared__ float4 sh4[TOPK];
    __shared__ float  sl[TOPK];
    __shared__ short  sidx[TOPK];
    __shared__ float  sGred[8];
    __shared__ int    sNs;
    int t = threadIdx.x;
    int Nk = d_Nk[b];
    for (int i = t; i < Nk; i += 256) { sh4[i] = d_hp4[b][i]; sl[i] = d_hlnp[b][i]; }
    if (t == 0) sNs = 0;
    __syncthreads();

    float y0 = (float)ty0, y1 = (float)(ty0 + 15);
    float x0 = (float)tx0, x1 = (float)(tx0 + 15);
    float ubv[2]; int bk[2];
    float myG = -3.4e38f;
    #pragma unroll
    for (int r = 0; r < 2; r++) {
        int k = t + r * 256;
        float u = -3.4e38f;
        if (k < Nk) {
            float4 h = sh4[k];
            float dy = fmaxf(fmaxf(y0 - h.x, h.x - y1), 0.0f);
            float dx = fmaxf(fmaxf(x0 - h.y, h.y - x1), 0.0f);
            float My = fmaxf(y1 - h.x, h.x - y0);
            float Mx = fmaxf(x1 - h.y, h.y - x0);
            float zy = dy * h.z, zx = dx * h.w;
            float Zy = My * h.z, Zx = Mx * h.w;
            u = fmaf(-0.5f, fmaf(zy, zy, zx * zx), sl[k]);
            float l = fmaf(-0.5f, fmaf(Zy, Zy, Zx * Zx), sl[k]);
            myG = fmaxf(myG, l);
        }
        ubv[r] = u; bk[r] = k;
    }
    #pragma unroll
    for (int off = 16; off; off >>= 1) myG = fmaxf(myG, __shfl_xor_sync(0xffffffffu, myG, off));
    if ((t & 31) == 0) sGred[t >> 5] = myG;
    __syncthreads();
    if (t < 8) {
        float g = sGred[t];
        #pragma unroll
        for (int off = 4; off; off >>= 1) g = fmaxf(g, __shfl_xor_sync(0xffu, g, off));
        if (t == 0) sGred[0] = g;
    }
    __syncthreads();
    float G = sGred[0] - 1e-3f;
    #pragma unroll
    for (int r = 0; r < 2; r++) {
        if (bk[r] < Nk && ubv[r] >= G) {
            int pos = atomicAdd(&sNs, 1);
            sidx[pos] = (short)bk[r];
        }
    }
    __syncthreads();
    int Ns = sNs;

    int py = ty0 + (t >> 4), px = tx0 + (t & 15);
    float fy = (float)py, fx = (float)px;
    float m = -1e30f;
    for (int q = 0; q < Ns; q++) {
        int k = sidx[q];
        float4 h = sh4[k];
        float zy = (fy - h.x) * h.z;
        float zx = (fx - h.y) * h.w;
        float e = fmaf(zy, zy, zx * zx);
        m = fmaxf(m, fmaf(-0.5f, e, sl[k]));
    }
    out[b * HW + py * Wd + px] = expf(m);
}

// ---------------- launch ----------------
extern "C" void kernel_launch(void* const* d_in, const int* in_sizes, int n_in,
                              void* d_out, int out_size)
{
    const float* mask = (const float*)d_in[0];
    const float* bias = (const float*)d_in[1];
    float* out = (float*)d_out;

    k1_score<<<(BN * (HW/4) + 255) / 256, 256>>>(mask, bias, out);
    kb1_sort<<<BN, NT1>>>();
    { dim3 g(PRE_K / 16, BN); k5_iou<<<g, 512>>>(); }
    kb2_nms_select<<<BN, 1024>>>(out);
    { dim3 g(100, BN);        k8_heat<<<g, 256>>>(out); }
}

// round 17
// speedup vs baseline: 1.6352x; 1.6352x over previous
#include <cuda_runtime.h>
#include <math.h>

#define BN 4
#define HW 25600
#define Wd 160
#define PRE_K 2048
#define TOPK 500
#define NT1 1024

#define OFF_MASK (BN*HW)                 /* 102400 */
#define OFF_BOX  (OFF_MASK + BN*4*HW)    /* 512000 */
#define OFF_VAL  (OFF_BOX + BN*TOPK*4)   /* 520000 */

// ---------------- scratch (device globals; no allocation) ----------------
__device__ float               d_score[BN][HW];
__device__ float4              d_boxes4[BN][HW];
__device__ unsigned long long  d_vkey[BN][HW];      // fallback path only
__device__ float               d_cscore[BN][PRE_K];
__device__ float4              d_cbox[BN][PRE_K];
__device__ unsigned long long  d_mask[BN][PRE_K][32];
__device__ int                 d_Vc[BN];
__device__ int                 d_Nk[BN];
__device__ float4              d_hp4[BN][TOPK];
__device__ float               d_hlnp[BN][TOPK];

// ---------------- K1: f32 softmax score + boxes + fused mask pass-through ----------------
// 1 pixel/thread, 400 blocks: 4x warps vs the float4 version -> latency-bound load/expf
// chains overlap across warps instead of serializing inside one thread.
__global__ void __launch_bounds__(256) k1_score(const float* __restrict__ mask,
                                                const float* __restrict__ bias,
                                                float* __restrict__ out)
{
    int idx = blockIdx.x * 256 + threadIdx.x;
    if (idx >= BN * HW) return;
    int b = idx / HW, p = idx - b * HW;
    const float* mk = mask + (size_t)b * 4 * HW;
    const float* bi = bias + (size_t)b * 4 * HW;
    float* mo = out + OFF_MASK + (size_t)b * 4 * HW;
    float x0 = mk[p], x1 = mk[HW + p], x2 = mk[2*HW + p], x3 = mk[3*HW + p];
    float h0 = bi[p], h1 = bi[HW + p], h2 = bi[2*HW + p], h3 = bi[3*HW + p];
    mo[p] = x0; mo[HW + p] = x1; mo[2*HW + p] = x2; mo[3*HW + p] = x3;   // pass-through
    float mm = x0; int cl = 0;
    if (x1 > mm) { mm = x1; cl = 1; }
    if (x2 > mm) { mm = x2; cl = 2; }
    if (x3 > mm) { mm = x3; cl = 3; }
    float e0 = expf(x0 - mm), e1 = expf(x1 - mm), e2 = expf(x2 - mm), e3 = expf(x3 - mm);
    float s = ((e0 + e1) + e2) + e3;
    float prob = 1.0f / s;
    bool fr = (cl != 0) && (prob > 0.75f);
    d_score[b][p] = fr ? prob : -1.0f;
    float y = (float)(p / Wd), x = (float)(p % Wd);
    d_boxes4[b][p] = make_float4(y + h0, x + h1, y + h2, x + h3);
}

// ---------------- KB1: compact + bitonic top-2048 sort + padding (per image) ----------------
__global__ void __launch_bounds__(NT1) kb1_sort()
{
    __shared__ unsigned long long skey[PRE_K];      // 16 KB
    __shared__ int spad[PRE_K];                     // 8 KB
    __shared__ int sprefV[800];
    __shared__ int swsum[32];
    __shared__ int sTot;
    int b = blockIdx.x;
    int t = threadIdx.x, lane = t & 31, w = t >> 5;

    unsigned flags = 0;
    unsigned kb[25];
    #pragma unroll
    for (int c = 0; c < 25; c++) {
        float sc = d_score[b][c * NT1 + t];
        bool fv = sc > 0.0f;
        kb[c] = ~__float_as_uint(sc);
        flags |= (fv ? 1u : 0u) << c;
        unsigned bal = __ballot_sync(0xffffffffu, fv);
        if (lane == 0) sprefV[c * 32 + w] = __popc(bal);
    }
    __syncthreads();

    int cnt = (t < 800) ? sprefV[t] : 0;
    int inc = cnt;
    #pragma unroll
    for (int off = 1; off < 32; off <<= 1) {
        int u = __shfl_up_sync(0xffffffffu, inc, off);
        if (lane >= off) inc += u;
    }
    if (lane == 31) swsum[w] = inc;
    __syncthreads();
    if (w == 0) {
        int v2 = swsum[lane], i2 = v2;
        #pragma unroll
        for (int off = 1; off < 32; off <<= 1) {
            int u = __shfl_up_sync(0xffffffffu, i2, off);
            if (lane >= off) i2 += u;
        }
        swsum[lane] = i2 - v2;
        if (lane == 31) sTot = i2;
    }
    __syncthreads();
    int excl = swsum[w] + inc - cnt;
    if (t < 800) sprefV[t] = excl;
    __syncthreads();
    int V  = sTot;
    int Vc = V < PRE_K ? V : PRE_K;

    #pragma unroll
    for (int c = 0; c < 25; c++) {
        bool fv = (flags >> c) & 1u;
        unsigned bal = __ballot_sync(0xffffffffu, fv);
        int pvL = __popc(bal & ((1u << lane) - 1u));
        int e  = c * 32 + w;
        int pe = sprefV[e];
        int p  = c * NT1 + t;
        if (fv) {
            int posV = pe + pvL;
            unsigned long long key = (((unsigned long long)kb[c]) << 32) | (unsigned)p;
            if (V <= PRE_K) skey[posV] = key;
            else            d_vkey[b][posV] = key;
        } else {
            int posI = (e << 5) - pe + (lane - pvL);
            if (posI < PRE_K) spad[posI] = p;
        }
    }
    __syncthreads();

    if (V <= PRE_K) {
        int P = 1; while (P < V) P <<= 1;
        for (int s = V + t; s < P; s += NT1) skey[s] = ~0ull;
        __syncthreads();
        for (unsigned ksz = 2; ksz <= (unsigned)P; ksz <<= 1) {
            for (unsigned j = ksz >> 1; j; j >>= 1) {
                unsigned tt = (unsigned)t;
                if (tt < (unsigned)(P >> 1)) {
                    unsigned i  = ((tt & ~(j - 1)) << 1) | (tt & (j - 1));
                    unsigned pr = i | j;
                    bool asc = (i & ksz) == 0;
                    unsigned long long a = skey[i], cc = skey[pr];
                    if ((a > cc) == asc) { skey[i] = cc; skey[pr] = a; }
                }
                __syncthreads();
            }
        }
        for (int s = t; s < PRE_K; s += NT1) {
            int p; float sc_;
            if (s < Vc) {
                unsigned long long k = skey[s];
                p   = (int)(k & 0xffffffffu);
                sc_ = __uint_as_float(~(unsigned)(k >> 32));
            } else {
                p   = spad[s - Vc];
                sc_ = -1.0f;
            }
            d_cscore[b][s] = sc_;
            d_cbox[b][s]   = d_boxes4[b][p];
        }
    } else {
        int nR = (V + NT1 - 1) / NT1;
        for (int r0 = 0; r0 < nR; r0++) {
            int e = r0 * NT1 + t;
            unsigned long long ke = (e < V) ? d_vkey[b][e] : 0ull;
            int rk = 0;
            for (int base = 0; base < V; base += PRE_K) {
                int n = V - base; if (n > PRE_K) n = PRE_K;
                __syncthreads();
                for (int qq = t; qq < n; qq += NT1) skey[qq] = d_vkey[b][base + qq];
                __syncthreads();
                if (e < V) for (int j = 0; j < n; j++) rk += (skey[j] < ke) ? 1 : 0;
            }
            __syncthreads();
            if (e < V && rk < PRE_K) {
                int p = (int)(ke & 0xffffffffu);
                d_cscore[b][rk] = __uint_as_float(~(unsigned)(ke >> 32));
                d_cbox[b][rk]   = d_boxes4[b][p];
            }
        }
    }
    if (t == 0) d_Vc[b] = Vc;
}

// ---------------- K5: suppression bit-mask matrix, 8 rows/block, cbox in shared ----------------
__global__ void __launch_bounds__(256) k5_iou()
{
    __shared__ float4 scbox[PRE_K];                 // 32 KB
    int b = blockIdx.y;
    int Vc = d_Vc[b];
    int i0 = blockIdx.x * 8;
    if (i0 >= Vc) return;
    int tid = threadIdx.x;
    for (int q = tid; q < Vc; q += 256) scbox[q] = d_cbox[b][q];
    __syncthreads();
    int r = tid >> 5, lane = tid & 31;
    int i = i0 + r;
    if (i >= Vc) return;
    float4 a = scbox[i];
    float areaA = (a.z - a.x) * (a.w - a.y);
    unsigned long long bits = 0;
    int j0 = lane << 6;
    int ks = i + 1 - j0; if (ks < 0) ks = 0;
    int ke = Vc - j0;    if (ke > 64) ke = 64;
    for (int k = ks; k < ke; k++) {
        float4 c = scbox[j0 + k];
        float areaB = (c.z - c.x) * (c.w - c.y);
        float lty = fmaxf(a.x, c.x), ltx = fmaxf(a.y, c.y);
        float rby = fminf(a.z, c.z), rbx = fminf(a.w, c.w);
        float wy = fmaxf(rby - lty, 0.0f), wx = fmaxf(rbx - ltx, 0.0f);
        float inter = wy * wx;
        float iou = inter / (areaA + areaB - inter);  // IEEE div: bit-matches reference decision
        if (iou > 0.5f) bits |= 1ull << k;
    }
    d_mask[b][i][lane] = bits;
}

// ---------------- KB2: exact greedy NMS via iterative leader elimination (R12 version) ----------------
__global__ void __launch_bounds__(1024) kb2_nms_select(float* __restrict__ out)
{
    __shared__ unsigned long long s_red[128][33];   // [chunk][word] (+pad) 33.8 KB
    __shared__ unsigned long long s_alive[32], s_kept[32], s_lead[32];
    __shared__ int s_flag;
    __shared__ int wpref[33];
    int b = blockIdx.x;
    int t = threadIdx.x;
    int Vc = d_Vc[b];
    int chunk = t >> 3;          // 128 chunks x 16 rows
    int slot  = t & 7;           // 8 slots x 4 words
    const unsigned long long* mrow = &d_mask[b][0][0];

    if (t < 32) {
        int hi = Vc - t * 64;
        unsigned long long a = 0;
        if (hi >= 64) a = ~0ull;
        else if (hi > 0) a = (1ull << hi) - 1ull;
        s_alive[t] = a;
        s_kept[t] = 0;
        if (t == 0) s_flag = (Vc > 0);
    }
    __syncthreads();

    for (int round = 0; round < PRE_K && s_flag; round++) {
        {
            unsigned af = (unsigned)((s_alive[chunk >> 2] >> ((chunk & 3) * 16)) & 0xFFFFull);
            unsigned long long a0 = 0, a1 = 0, a2 = 0, a3 = 0;
            int rbase = chunk << 4;
            while (af) {
                int r = __ffs(af) - 1; af &= af - 1;
                const ulonglong2* p = (const ulonglong2*)(mrow + (size_t)(rbase + r) * 32 + slot * 4);
                ulonglong2 u = p[0], v = p[1];
                a0 |= u.x; a1 |= u.y; a2 |= v.x; a3 |= v.y;
            }
            s_red[chunk][slot*4+0] = a0; s_red[chunk][slot*4+1] = a1;
            s_red[chunk][slot*4+2] = a2; s_red[chunk][slot*4+3] = a3;
        }
        __syncthreads();
        if (t < 32) {
            unsigned long long r0 = 0, r1 = 0, r2 = 0, r3 = 0;
            #pragma unroll 4
            for (int c = 0; c < 128; c += 4) {
                r0 |= s_red[c][t]; r1 |= s_red[c+1][t];
                r2 |= s_red[c+2][t]; r3 |= s_red[c+3][t];
            }
            unsigned long long sup = r0 | r1 | r2 | r3;
            s_lead[t] = s_alive[t] & ~sup;           // leaders: kept for sure
        }
        __syncthreads();
        {
            unsigned lf = (unsigned)((s_lead[chunk >> 2] >> ((chunk & 3) * 16)) & 0xFFFFull);
            unsigned long long a0 = 0, a1 = 0, a2 = 0, a3 = 0;
            int rbase = chunk << 4;
            while (lf) {
                int r = __ffs(lf) - 1; lf &= lf - 1;
                const ulonglong2* p = (const ulonglong2*)(mrow + (size_t)(rbase + r) * 32 + slot * 4);
                ulonglong2 u = p[0], v = p[1];
                a0 |= u.x; a1 |= u.y; a2 |= v.x; a3 |= v.y;
            }
            s_red[chunk][slot*4+0] = a0; s_red[chunk][slot*4+1] = a1;
            s_red[chunk][slot*4+2] = a2; s_red[chunk][slot*4+3] = a3;
        }
        __syncthreads();
        if (t < 32) {
            unsigned long long r0 = 0, r1 = 0, r2 = 0, r3 = 0;
            #pragma unroll 4
            for (int c = 0; c < 128; c += 4) {
                r0 |= s_red[c][t]; r1 |= s_red[c+1][t];
                r2 |= s_red[c+2][t]; r3 |= s_red[c+3][t];
            }
            unsigned long long supL = r0 | r1 | r2 | r3;
            s_kept[t] |= s_lead[t];
            unsigned long long na = s_alive[t] & ~(s_lead[t] | supL);
            s_alive[t] = na;
            unsigned any = __ballot_sync(0xffffffffu, na != 0ull);
            if (t == 0) s_flag = (any != 0u);
        }
        __syncthreads();
    }

    if (t == 0) {
        int run = 0;
        for (int w = 0; w < 32; w++) { wpref[w] = run; run += __popcll(s_kept[w]); }
        wpref[32] = run;
        d_Nk[b] = run < TOPK ? run : TOPK;
    }
    __syncthreads();
    int keptTotal = wpref[32];
    for (int slot2 = t; slot2 < PRE_K; slot2 += 1024) {
        int w = slot2 >> 6, bo = slot2 & 63;
        unsigned long long word = s_kept[w];
        int bit = (int)((word >> bo) & 1ull);
        int kb2 = wpref[w] + __popcll(word & ((1ull << bo) - 1ull));
        int r = bit ? kb2 : keptTotal + (slot2 - kb2);
        if (r < TOPK) {
            float4 bx = d_cbox[b][slot2];
            ((float4*)(out + OFF_BOX))[b * TOPK + r] = bx;
            out[OFF_VAL + b * TOPK + r] = bit ? 1.0f : 0.0f;
            if (bit) {
                float sc = d_cscore[b][slot2];
                float sy = bx.z - bx.x, sx = bx.w - bx.y;
                d_hp4[b][r] = make_float4((bx.x + bx.z) * 0.5f, (bx.y + bx.w) * 0.5f,
                                          10.0f / sy, 10.0f / sx);
                d_hlnp[b][r] = logf(sc);
            }
        }
    }
}

// ---------------- K8: tile-pruned heatmap (exact interval pruning per 16x16 tile) ----------------
__global__ void __launch_bounds__(256) k8_heat(float* __restrict__ out)
{
    int b = blockIdx.y;
    int tile = blockIdx.x;                          // 100 tiles of 16x16
    int ty0 = (tile / 10) * 16, tx0 = (tile % 10) * 16;
    __shared__ float4 sh4[TOPK];
    __shared__ float  sl[TOPK];
    __shared__ short  sidx[TOPK];
    __shared__ float  sGred[8];
    __shared__ int    sNs;
    int t = threadIdx.x;
    int Nk = d_Nk[b];
    for (int i = t; i < Nk; i += 256) { sh4[i] = d_hp4[b][i]; sl[i] = d_hlnp[b][i]; }
    if (t == 0) sNs = 0;
    __syncthreads();

    float y0 = (float)ty0, y1 = (float)(ty0 + 15);
    float x0 = (float)tx0, x1 = (float)(tx0 + 15);
    float ubv[2]; int bk[2];
    float myG = -3.4e38f;
    #pragma unroll
    for (int r = 0; r < 2; r++) {
        int k = t + r * 256;
        float u = -3.4e38f;
        if (k < Nk) {
            float4 h = sh4[k];
            float dy = fmaxf(fmaxf(y0 - h.x, h.x - y1), 0.0f);
            float dx = fmaxf(fmaxf(x0 - h.y, h.y - x1), 0.0f);
            float My = fmaxf(y1 - h.x, h.x - y0);
            float Mx = fmaxf(x1 - h.y, h.y - x0);
            float zy = dy * h.z, zx = dx * h.w;
            float Zy = My * h.z, Zx = Mx * h.w;
            u = fmaf(-0.5f, fmaf(zy, zy, zx * zx), sl[k]);
            float l = fmaf(-0.5f, fmaf(Zy, Zy, Zx * Zx), sl[k]);
            myG = fmaxf(myG, l);
        }
        ubv[r] = u; bk[r] = k;
    }
    #pragma unroll
    for (int off = 16; off; off >>= 1) myG = fmaxf(myG, __shfl_xor_sync(0xffffffffu, myG, off));
    if ((t & 31) == 0) sGred[t >> 5] = myG;
    __syncthreads();
    if (t < 8) {
        float g = sGred[t];
        #pragma unroll
        for (int off = 4; off; off >>= 1) g = fmaxf(g, __shfl_xor_sync(0xffu, g, off));
        if (t == 0) sGred[0] = g;
    }
    __syncthreads();
    float G = sGred[0] - 1e-3f;
    #pragma unroll
    for (int r = 0; r < 2; r++) {
        if (bk[r] < Nk && ubv[r] >= G) {
            int pos = atomicAdd(&sNs, 1);
            sidx[pos] = (short)bk[r];
        }
    }
    __syncthreads();
    int Ns = sNs;

    int py = ty0 + (t >> 4), px = tx0 + (t & 15);
    float fy = (float)py, fx = (float)px;
    float m = -1e30f;
    for (int q = 0; q < Ns; q++) {
        int k = sidx[q];
        float4 h = sh4[k];
        float zy = (fy - h.x) * h.z;
        float zx = (fx - h.y) * h.w;
        float e = fmaf(zy, zy, zx * zx);
        m = fmaxf(m, fmaf(-0.5f, e, sl[k]));
    }
    out[b * HW + py * Wd + px] = expf(m);
}

// ---------------- launch ----------------
extern "C" void kernel_launch(void* const* d_in, const int* in_sizes, int n_in,
                              void* d_out, int out_size)
{
    const float* mask = (const float*)d_in[0];
    const float* bias = (const float*)d_in[1];
    float* out = (float*)d_out;

    k1_score<<<(BN * HW + 255) / 256, 256>>>(mask, bias, out);
    kb1_sort<<<BN, NT1>>>();
    { dim3 g(PRE_K / 8, BN); k5_iou<<<g, 256>>>(); }
    kb2_nms_select<<<BN, 1024>>>(out);
    { dim3 g(100, BN);       k8_heat<<<g, 256>>>(out); }
}